// round 2
// baseline (speedup 1.0000x reference)
#include <cuda_runtime.h>

#define HW 512
#define PLANE (512*512)
#define TPB 256
#define WPB 8   // warps per block

// 0.5*cos(m*pi/16) constants and 1/sqrt(8)
#define DA  0.35355339059327373f
#define DB1 0.46193976625564337f
#define DB3 0.19134171618254492f
#define DC1 0.49039264020161522f
#define DC3 0.41573480615127262f
#define DC5 0.27778511650980114f
#define DC7 0.09754516100806417f

// in-place v = D * v (D = type-II DCT matrix, matches reference _dct_matrix cast to f32)
__device__ __forceinline__ void mulD(float v[8]) {
    float s0 = v[0] + v[7], s1 = v[1] + v[6], s2 = v[2] + v[5], s3 = v[3] + v[4];
    float d0 = v[0] - v[7], d1 = v[1] - v[6], d2 = v[2] - v[5], d3 = v[3] - v[4];
    float t0 = s0 + s3, t1 = s1 + s2, t2 = s0 - s3, t3 = s1 - s2;
    v[0] = DA * (t0 + t1);
    v[4] = DA * (t0 - t1);
    v[2] = fmaf(DB1, t2,  DB3 * t3);
    v[6] = fmaf(DB3, t2, -DB1 * t3);
    v[1] = fmaf(DC1, d0, fmaf( DC3, d1, fmaf( DC5, d2,  DC7 * d3)));
    v[3] = fmaf(DC3, d0, fmaf(-DC7, d1, fmaf(-DC1, d2, -DC5 * d3)));
    v[5] = fmaf(DC5, d0, fmaf(-DC1, d1, fmaf( DC7, d2,  DC3 * d3)));
    v[7] = fmaf(DC7, d0, fmaf(-DC5, d1, fmaf( DC3, d2, -DC1 * d3)));
}

// in-place v = D^T * v
__device__ __forceinline__ void mulDT(float v[8]) {
    float ee0 = DA * (v[0] + v[4]);
    float ee1 = DA * (v[0] - v[4]);
    float eb0 = fmaf(DB1, v[2],  DB3 * v[6]);
    float eb1 = fmaf(DB3, v[2], -DB1 * v[6]);
    float E0 = ee0 + eb0, E3 = ee0 - eb0;
    float E1 = ee1 + eb1, E2 = ee1 - eb1;
    float O0 = fmaf(DC1, v[1], fmaf( DC3, v[3], fmaf( DC5, v[5],  DC7 * v[7])));
    float O1 = fmaf(DC3, v[1], fmaf(-DC7, v[3], fmaf(-DC1, v[5], -DC5 * v[7])));
    float O2 = fmaf(DC5, v[1], fmaf(-DC1, v[3], fmaf( DC7, v[5],  DC3 * v[7])));
    float O3 = fmaf(DC7, v[1], fmaf(-DC5, v[3], fmaf( DC3, v[5], -DC1 * v[7])));
    v[0] = E0 + O0; v[7] = E0 - O0;
    v[1] = E1 + O1; v[6] = E1 - O1;
    v[2] = E2 + O2; v[5] = E2 - O2;
    v[3] = E3 + O3; v[4] = E3 - O3;
}

// conflict-free 8x8 transpose within a tile via padded smem ([8][9] region per tile)
__device__ __forceinline__ void transp(float v[8], float* tsq, int q) {
    #pragma unroll
    for (int i = 0; i < 8; i++) tsq[i * 9 + q] = v[i];
    __syncwarp();
    float tmp[8];
    #pragma unroll
    for (int i = 0; i < 8; i++) tmp[i] = tsq[q * 9 + i];
    __syncwarp();
    #pragma unroll
    for (int i = 0; i < 8; i++) v[i] = tmp[i];
}

// forward DCT (ref: coef = D X D), soft quant, inverse (ref: rec = D^T Q D^T)
__device__ __forceinline__ void proc_channel(float v[8], const float qv[8], const float qi[8],
                                             float* tsq, int q) {
    // coef^T layout: lane q ends holding coef[q][l] in reg l
    mulD(v);
    transp(v, tsq, q);
    mulDT(v);
    // soft-round quantization: exact sum of 20 sigmoids collapses to 1 (TEMP=50 saturation)
    #pragma unroll
    for (int l = 0; l < 8; l++) {
        float x = v[l] * qi[l];
        float n = floorf(x);
        n = fmaxf(-10.0f, fminf(n, 9.0f));
        float z = 50.0f * (x - n - 0.5f);
        float e = __expf(-z);
        float s = __fdividef(1.0f, 1.0f + e);
        v[l] = (n + s) * qv[l];
    }
    mulD(v);
    transp(v, tsq, q);
    mulDT(v);
}

__global__ void __launch_bounds__(TPB)
jpeg_kernel(const float* __restrict__ img, const float* __restrict__ q_y,
            const float* __restrict__ q_c, float* __restrict__ out) {
    __shared__ float ts[WPB][4][8][9];

    const int warpLocal = threadIdx.x >> 5;
    const int lane = threadIdx.x & 31;
    const int t = lane >> 3;   // tile within warp's 4-tile group
    const int q = lane & 7;    // column within tile

    const int w = blockIdx.x * WPB + warpLocal;   // global warp id
    const int b = w >> 10;                         // 1024 warps per image (64 tile-rows * 16 spans)
    const int rem = w & 1023;
    const int tr = rem >> 4;                       // tile row
    const int sp = rem & 15;                       // 32-column span
    const int col = (sp << 5) + lane;
    const int row0 = tr << 3;

    const float* base = img + (size_t)b * 3 * PLANE + (size_t)row0 * HW + col;

    // Load RGB columns (coalesced 128B per warp per row), clip, color transform
    float Y[8], Cb[8], Cr[8];
    #pragma unroll
    for (int r = 0; r < 8; r++) {
        float R = __saturatef(base[r * HW]);
        float G = __saturatef(base[PLANE + r * HW]);
        float B = __saturatef(base[2 * PLANE + r * HW]);
        Y[r]  = 0.299f * R + 0.587f * G + 0.114f * B;
        Cb[r] = -0.168736f * R - 0.331264f * G + 0.5f * B + 0.5f;
        Cr[r] = 0.5f * R - 0.418688f * G - 0.081312f * B + 0.5f;
    }

    // Quant tables for this lane's coef row q (clipped to [2,15]); L1-resident
    float qvy[8], qiy[8], qvc[8], qic[8];
    #pragma unroll
    for (int l = 0; l < 8; l++) {
        float a = q_y[q * 8 + l];
        a = fminf(fmaxf(a, 2.0f), 15.0f);
        qvy[l] = a; qiy[l] = 1.0f / a;
        float c = q_c[q * 8 + l];
        c = fminf(fmaxf(c, 2.0f), 15.0f);
        qvc[l] = c; qic[l] = 1.0f / c;
    }

    float* tsq = &ts[warpLocal][t][0][0];
    proc_channel(Y,  qvy, qiy, tsq, q);
    proc_channel(Cb, qvc, qic, tsq, q);
    proc_channel(Cr, qvc, qic, tsq, q);

    // Inverse color transform + clip + coalesced store
    float* obase = out + (size_t)b * 3 * PLANE + (size_t)row0 * HW + col;
    #pragma unroll
    for (int r = 0; r < 8; r++) {
        float y2 = Y[r], cb2 = Cb[r] - 0.5f, cr2 = Cr[r] - 0.5f;
        float R = y2 + 1.402f * cr2;
        float G = y2 - 0.344136f * cb2 - 0.714136f * cr2;
        float B = y2 + 1.772f * cb2;
        obase[r * HW]             = __saturatef(R);
        obase[PLANE + r * HW]     = __saturatef(G);
        obase[2 * PLANE + r * HW] = __saturatef(B);
    }
}

extern "C" void kernel_launch(void* const* d_in, const int* in_sizes, int n_in,
                              void* d_out, int out_size) {
    const float* img = (const float*)d_in[0];
    const float* qy  = (const float*)d_in[1];
    const float* qc  = (const float*)d_in[2];
    float* out = (float*)d_out;

    int nb = in_sizes[0] / (3 * HW * HW);          // batch (8)
    int warps = nb * (HW / 8) * (HW / 32);         // nb * 64 * 16
    int blocks = warps / WPB;                      // 1024 for nb=8
    jpeg_kernel<<<blocks, TPB>>>(img, qy, qc, out);
}

// round 3
// speedup vs baseline: 1.1382x; 1.1382x over previous
#include <cuda_runtime.h>

#define HW 512
#define PLANE (512*512)
#define TPB 256
#define WPB 8   // warps per block

// 0.5*cos(m*pi/16) constants and 1/sqrt(8)
#define DA  0.35355339059327373f
#define DB1 0.46193976625564337f
#define DB3 0.19134171618254492f
#define DC1 0.49039264020161522f
#define DC3 0.41573480615127262f
#define DC5 0.27778511650980114f
#define DC7 0.09754516100806417f

typedef unsigned long long u64;

// ---- packed f32x2 helpers (Blackwell SIMD fp32, PTX-only) ----
__device__ __forceinline__ u64 PK(float a, float b) {
    u64 r; asm("mov.b64 %0,{%1,%2};" : "=l"(r) : "f"(a), "f"(b)); return r;
}
__device__ __forceinline__ void UPK(u64 v, float& a, float& b) {
    asm("mov.b64 {%0,%1},%2;" : "=f"(a), "=f"(b) : "l"(v));
}
__device__ __forceinline__ u64 fadd2(u64 a, u64 b) {
    u64 r; asm("add.rn.f32x2 %0,%1,%2;" : "=l"(r) : "l"(a), "l"(b)); return r;
}
__device__ __forceinline__ u64 fmul2(u64 a, u64 b) {
    u64 r; asm("mul.rn.f32x2 %0,%1,%2;" : "=l"(r) : "l"(a), "l"(b)); return r;
}
__device__ __forceinline__ u64 ffma2(u64 a, u64 b, u64 c) {
    u64 r; asm("fma.rn.f32x2 %0,%1,%2,%3;" : "=l"(r) : "l"(a), "l"(b), "l"(c)); return r;
}
// a - b  ==  b * (-1) + a   (sub.f32x2 availability unverified; fma is confirmed)
__device__ __forceinline__ u64 fsub2(u64 a, u64 b) {
    return ffma2(b, PK(-1.0f, -1.0f), a);
}

// ---- scalar DCT (immediate-operand FFMA) ----
__device__ __forceinline__ void mulD(float v[8]) {
    float s0 = v[0] + v[7], s1 = v[1] + v[6], s2 = v[2] + v[5], s3 = v[3] + v[4];
    float d0 = v[0] - v[7], d1 = v[1] - v[6], d2 = v[2] - v[5], d3 = v[3] - v[4];
    float t0 = s0 + s3, t1 = s1 + s2, t2 = s0 - s3, t3 = s1 - s2;
    v[0] = DA * (t0 + t1);
    v[4] = DA * (t0 - t1);
    v[2] = fmaf(DB1, t2,  DB3 * t3);
    v[6] = fmaf(DB3, t2, -DB1 * t3);
    v[1] = fmaf(DC1, d0, fmaf( DC3, d1, fmaf( DC5, d2,  DC7 * d3)));
    v[3] = fmaf(DC3, d0, fmaf(-DC7, d1, fmaf(-DC1, d2, -DC5 * d3)));
    v[5] = fmaf(DC5, d0, fmaf(-DC1, d1, fmaf( DC7, d2,  DC3 * d3)));
    v[7] = fmaf(DC7, d0, fmaf(-DC5, d1, fmaf( DC3, d2, -DC1 * d3)));
}

__device__ __forceinline__ void mulDT(float v[8]) {
    float ee0 = DA * (v[0] + v[4]);
    float ee1 = DA * (v[0] - v[4]);
    float eb0 = fmaf(DB1, v[2],  DB3 * v[6]);
    float eb1 = fmaf(DB3, v[2], -DB1 * v[6]);
    float E0 = ee0 + eb0, E3 = ee0 - eb0;
    float E1 = ee1 + eb1, E2 = ee1 - eb1;
    float O0 = fmaf(DC1, v[1], fmaf( DC3, v[3], fmaf( DC5, v[5],  DC7 * v[7])));
    float O1 = fmaf(DC3, v[1], fmaf(-DC7, v[3], fmaf(-DC1, v[5], -DC5 * v[7])));
    float O2 = fmaf(DC5, v[1], fmaf(-DC1, v[3], fmaf( DC7, v[5],  DC3 * v[7])));
    float O3 = fmaf(DC7, v[1], fmaf(-DC5, v[3], fmaf( DC3, v[5], -DC1 * v[7])));
    v[0] = E0 + O0; v[7] = E0 - O0;
    v[1] = E1 + O1; v[6] = E1 - O1;
    v[2] = E2 + O2; v[5] = E2 - O2;
    v[3] = E3 + O3; v[4] = E3 - O3;
}

// ---- packed f32x2 DCT (Cb,Cr together) ----
__device__ __forceinline__ void mulD2(u64 v[8]) {
    const u64 CA  = PK(DA,  DA),  CB1 = PK(DB1, DB1), CB3 = PK(DB3, DB3);
    const u64 C1  = PK(DC1, DC1), C3  = PK(DC3, DC3);
    const u64 C5  = PK(DC5, DC5), C7  = PK(DC7, DC7);
    u64 s0 = fadd2(v[0], v[7]), s1 = fadd2(v[1], v[6]);
    u64 s2 = fadd2(v[2], v[5]), s3 = fadd2(v[3], v[4]);
    u64 d0 = fsub2(v[0], v[7]), d1 = fsub2(v[1], v[6]);
    u64 d2 = fsub2(v[2], v[5]), d3 = fsub2(v[3], v[4]);
    u64 t0 = fadd2(s0, s3), t1 = fadd2(s1, s2);
    u64 t2 = fsub2(s0, s3), t3 = fsub2(s1, s2);
    v[0] = fmul2(fadd2(t0, t1), CA);
    v[4] = fmul2(fsub2(t0, t1), CA);
    v[2] = ffma2(t2, CB1, fmul2(t3, CB3));
    v[6] = fsub2(fmul2(t2, CB3), fmul2(t3, CB1));
    v[1] = ffma2(d0, C1, ffma2(d1, C3, ffma2(d2, C5, fmul2(d3, C7))));
    v[3] = fsub2(fmul2(d0, C3), ffma2(d1, C7, ffma2(d2, C1, fmul2(d3, C5))));
    v[5] = fsub2(ffma2(d0, C5, ffma2(d2, C7, fmul2(d3, C3))), fmul2(d1, C1));
    v[7] = fsub2(ffma2(d0, C7, fmul2(d2, C3)), ffma2(d1, C5, fmul2(d3, C1)));
}

__device__ __forceinline__ void mulDT2(u64 v[8]) {
    const u64 CA  = PK(DA,  DA),  CB1 = PK(DB1, DB1), CB3 = PK(DB3, DB3);
    const u64 C1  = PK(DC1, DC1), C3  = PK(DC3, DC3);
    const u64 C5  = PK(DC5, DC5), C7  = PK(DC7, DC7);
    u64 ee0 = fmul2(fadd2(v[0], v[4]), CA);
    u64 ee1 = fmul2(fsub2(v[0], v[4]), CA);
    u64 eb0 = ffma2(v[2], CB1, fmul2(v[6], CB3));
    u64 eb1 = fsub2(fmul2(v[2], CB3), fmul2(v[6], CB1));
    u64 E0 = fadd2(ee0, eb0), E3 = fsub2(ee0, eb0);
    u64 E1 = fadd2(ee1, eb1), E2 = fsub2(ee1, eb1);
    u64 O0 = ffma2(v[1], C1, ffma2(v[3], C3, ffma2(v[5], C5, fmul2(v[7], C7))));
    u64 O1 = fsub2(fmul2(v[1], C3), ffma2(v[3], C7, ffma2(v[5], C1, fmul2(v[7], C5))));
    u64 O2 = fsub2(ffma2(v[1], C5, ffma2(v[5], C7, fmul2(v[7], C3))), fmul2(v[3], C1));
    u64 O3 = fsub2(ffma2(v[1], C7, fmul2(v[5], C3)), ffma2(v[3], C5, fmul2(v[7], C1)));
    v[0] = fadd2(E0, O0); v[7] = fsub2(E0, O0);
    v[1] = fadd2(E1, O1); v[6] = fsub2(E1, O1);
    v[2] = fadd2(E2, O2); v[5] = fsub2(E2, O2);
    v[3] = fadd2(E3, O3); v[4] = fsub2(E3, O3);
}

// ---- transposes via padded smem (conflict-free both phases) ----
__device__ __forceinline__ void transpF(float v[8], float* tsq, int q) {
    #pragma unroll
    for (int i = 0; i < 8; i++) tsq[i * 9 + q] = v[i];
    __syncwarp();
    float tmp[8];
    #pragma unroll
    for (int i = 0; i < 8; i++) tmp[i] = tsq[q * 9 + i];
    __syncwarp();
    #pragma unroll
    for (int i = 0; i < 8; i++) v[i] = tmp[i];
}

__device__ __forceinline__ void transp2(u64 v[8], u64* tsq, int q) {
    #pragma unroll
    for (int i = 0; i < 8; i++) tsq[i * 9 + q] = v[i];
    __syncwarp();
    u64 tmp[8];
    #pragma unroll
    for (int i = 0; i < 8; i++) tmp[i] = tsq[q * 9 + i];
    __syncwarp();
    #pragma unroll
    for (int i = 0; i < 8; i++) v[i] = tmp[i];
}

// saturated-sigmoid soft-round: exact collapse of the 20-term sum at TEMP=50
__device__ __forceinline__ float quant_s(float v, float qi, float qv) {
    float x = v * qi;
    float n = floorf(x);
    n = fmaxf(-10.0f, fminf(n, 9.0f));
    float t = x - n;
    float e = __expf(fmaf(-50.0f, t, 25.0f));   // exp(-50*(t-0.5))
    float s = __fdividef(1.0f, 1.0f + e);
    return (n + s) * qv;
}

__global__ void __launch_bounds__(TPB)
jpeg_kernel(const float* __restrict__ img, const float* __restrict__ q_y,
            const float* __restrict__ q_c, float* __restrict__ out) {
    __shared__ float tsf[WPB][4][8][9];     // scalar transpose scratch (Y)
    __shared__ u64   ts2[WPB][4][8][9];     // packed transpose scratch (CbCr)
    __shared__ float tqvy[72], tqiy[72], tqvc[72], tqic[72];  // stride-9 padded tables

    const int tid = threadIdx.x;

    // one-time per block: clipped quant tables + precise reciprocals into smem
    if (tid < 128) {
        int which = tid >> 6;          // 0 = luma, 1 = chroma
        int idx = tid & 63;
        const float* src = which ? q_c : q_y;
        float a = src[idx];
        a = fminf(fmaxf(a, 2.0f), 15.0f);
        int o = (idx >> 3) * 9 + (idx & 7);
        if (which) { tqvc[o] = a; tqic[o] = 1.0f / a; }
        else       { tqvy[o] = a; tqiy[o] = 1.0f / a; }
    }
    __syncthreads();

    const int warpLocal = tid >> 5;
    const int lane = tid & 31;
    const int t = lane >> 3;   // tile within warp's 4-tile group
    const int q = lane & 7;    // column within tile

    const int w = blockIdx.x * WPB + warpLocal;
    const int b = w >> 10;                 // 1024 warps per image
    const int rem = w & 1023;
    const int tr = rem >> 4;               // tile row
    const int sp = rem & 15;               // 32-column span
    const int col = (sp << 5) + lane;
    const int row0 = tr << 3;

    const float* base = img + (size_t)b * 3 * PLANE + (size_t)row0 * HW + col;

    // color-transform constants for packed (cb,cr): lo = cb, hi = cr
    const u64 KRC = PK(-0.168736f,  0.5f);
    const u64 KGC = PK(-0.331264f, -0.418688f);
    const u64 KBC = PK( 0.5f,      -0.081312f);
    const u64 HALF2 = PK(0.5f, 0.5f);

    float Y[8];
    u64   C[8];
    #pragma unroll
    for (int r = 0; r < 8; r++) {
        float R = __saturatef(base[r * HW]);
        float G = __saturatef(base[PLANE + r * HW]);
        float B = __saturatef(base[2 * PLANE + r * HW]);
        Y[r] = 0.299f * R + 0.587f * G + 0.114f * B;
        C[r] = ffma2(PK(R, R), KRC, ffma2(PK(G, G), KGC, ffma2(PK(B, B), KBC, HALF2)));
    }

    float* tfq = &tsf[warpLocal][t][0][0];
    u64*   t2q = &ts2[warpLocal][t][0][0];
    const int q9 = q * 9;

    // ---- Y channel (scalar) ----
    mulD(Y);
    transpF(Y, tfq, q);
    mulDT(Y);
    #pragma unroll
    for (int l = 0; l < 8; l++)
        Y[l] = quant_s(Y[l], tqiy[q9 + l], tqvy[q9 + l]);
    mulD(Y);
    transpF(Y, tfq, q);
    mulDT(Y);

    // ---- Cb+Cr channels (packed f32x2) ----
    mulD2(C);
    transp2(C, t2q, q);
    mulDT2(C);
    #pragma unroll
    for (int l = 0; l < 8; l++) {
        float cb, cr;
        UPK(C[l], cb, cr);
        float qi = tqic[q9 + l], qv = tqvc[q9 + l];
        cb = quant_s(cb, qi, qv);
        cr = quant_s(cr, qi, qv);
        C[l] = PK(cb, cr);
    }
    mulD2(C);
    transp2(C, t2q, q);
    mulDT2(C);

    // inverse color transform + clip + coalesced store
    float* obase = out + (size_t)b * 3 * PLANE + (size_t)row0 * HW + col;
    #pragma unroll
    for (int r = 0; r < 8; r++) {
        float cb, cr;
        UPK(C[r], cb, cr);
        cb -= 0.5f; cr -= 0.5f;
        float y2 = Y[r];
        float R = y2 + 1.402f * cr;
        float G = y2 - 0.344136f * cb - 0.714136f * cr;
        float B = y2 + 1.772f * cb;
        obase[r * HW]             = __saturatef(R);
        obase[PLANE + r * HW]     = __saturatef(G);
        obase[2 * PLANE + r * HW] = __saturatef(B);
    }
}

extern "C" void kernel_launch(void* const* d_in, const int* in_sizes, int n_in,
                              void* d_out, int out_size) {
    const float* img = (const float*)d_in[0];
    const float* qy  = (const float*)d_in[1];
    const float* qc  = (const float*)d_in[2];
    float* out = (float*)d_out;

    int nb = in_sizes[0] / (3 * HW * HW);          // batch (8)
    int warps = nb * (HW / 8) * (HW / 32);         // nb * 64 * 16
    int blocks = warps / WPB;                      // 1024 for nb=8
    jpeg_kernel<<<blocks, TPB>>>(img, qy, qc, out);
}